// round 1
// baseline (speedup 1.0000x reference)
#include <cuda_runtime.h>
#include <cstdint>

#define NB 64
#define NT 2048
#define NM 1024
#define NA 512
#define NQ 1024

#define BM 64      // rows (t) per CTA
#define KC 16      // k-chunk
#define RS 20      // smem row stride in floats (pad: conflict-free, 16B-aligned)
#define NCHUNK (NM / KC)

__device__ float g_wq[NB * NA];  // query @ W_query.T

__device__ __forceinline__ unsigned f2tf(float x) {
    unsigned r;
    asm("cvt.rna.tf32.f32 %0, %1;" : "=r"(r) : "f"(x));
    return r;
}

__device__ __forceinline__ void mma_tf32(float& d0, float& d1, float& d2, float& d3,
                                         unsigned a0, unsigned a1, unsigned a2, unsigned a3,
                                         unsigned b0, unsigned b1) {
    asm("mma.sync.aligned.m16n8k8.row.col.f32.tf32.tf32.f32 "
        "{%0,%1,%2,%3},{%4,%5,%6,%7},{%8,%9},{%0,%1,%2,%3};"
        : "+f"(d0), "+f"(d1), "+f"(d2), "+f"(d3)
        : "r"(a0), "r"(a1), "r"(a2), "r"(a3), "r"(b0), "r"(b1));
}

// ---------------------------------------------------------------------------
// Kernel 1: wq[b][a] = sum_k query[b][k] * W_query[a][k]   (fp32 exact, tiny)
// ---------------------------------------------------------------------------
__global__ void wq_kernel(const float* __restrict__ query, const float* __restrict__ Wq) {
    int b = blockIdx.x;
    int a = threadIdx.x;  // 512 threads
    const float4* q4 = (const float4*)(query + b * NQ);
    const float4* w4 = (const float4*)(Wq + a * NQ);
    float s = 0.f;
#pragma unroll 8
    for (int k = 0; k < NQ / 4; k++) {
        float4 q = q4[k], w = w4[k];
        s += q.x * w.x + q.y * w.y + q.z * w.z + q.w * w.w;
    }
    g_wq[b * NA + a] = s;
}

// ---------------------------------------------------------------------------
// Kernel 2: fused  wm = memory @ Wm.T (tf32 MMA)  ->  score = Wv . tanh(wq+wm)
// CTA: 64 rows x N=512 full.  8 warps, each 64x64 warp tile.
// ---------------------------------------------------------------------------
__global__ __launch_bounds__(256) void score_kernel(
    const float* __restrict__ mem, const float* __restrict__ Wm,
    const float* __restrict__ Wv, float* __restrict__ scores)
{
    extern __shared__ float smem[];
    float* As  = smem;                    // 2 * 64*20  = 2560 floats
    float* Bs  = smem + 2 * BM * RS;      // 2 * 512*20 = 20480 floats
    float* wqs = Bs + 2 * NA * RS;        // 512
    float* wvs = wqs + NA;                // 512
    float* sp  = wvs + NA;                // 8*64

    int tid = threadIdx.x;
    int wid = tid >> 5, lane = tid & 31;
    int g = lane >> 2, tg = lane & 3;
    int b = blockIdx.y, t0 = blockIdx.x * BM;

    for (int i = tid; i < NA; i += 256) {
        wqs[i] = g_wq[b * NA + i];
        wvs[i] = Wv[i];
    }

    const float* Ag = mem + ((size_t)b * NT + t0) * NM;

    float acc[4][8][4];
#pragma unroll
    for (int mf = 0; mf < 4; mf++)
#pragma unroll
        for (int j = 0; j < 8; j++)
#pragma unroll
            for (int q = 0; q < 4; q++) acc[mf][j][q] = 0.f;

    const int arow = tid >> 2, ac4 = tid & 3;
    uint4 ra, rb[8];

    // prologue: chunk 0 -> buf 0
    {
        float4 v = *(const float4*)(Ag + arow * NM + ac4 * 4);
        ra = make_uint4(f2tf(v.x), f2tf(v.y), f2tf(v.z), f2tf(v.w));
#pragma unroll
        for (int i = 0; i < 8; i++) {
            int e = tid + i * 256;
            int row = e >> 2, c4 = e & 3;
            float4 w = *(const float4*)(Wm + row * NM + c4 * 4);
            rb[i] = make_uint4(f2tf(w.x), f2tf(w.y), f2tf(w.z), f2tf(w.w));
        }
        *(uint4*)(As + arow * RS + ac4 * 4) = ra;
#pragma unroll
        for (int i = 0; i < 8; i++) {
            int e = tid + i * 256;
            int row = e >> 2, c4 = e & 3;
            *(uint4*)(Bs + row * RS + c4 * 4) = rb[i];
        }
    }
    __syncthreads();

    for (int c = 0; c < NCHUNK; c++) {
        int cur = c & 1;
        if (c < NCHUNK - 1) {  // prefetch next chunk into registers
            int k0 = (c + 1) * KC;
            float4 v = *(const float4*)(Ag + arow * NM + k0 + ac4 * 4);
            ra = make_uint4(f2tf(v.x), f2tf(v.y), f2tf(v.z), f2tf(v.w));
#pragma unroll
            for (int i = 0; i < 8; i++) {
                int e = tid + i * 256;
                int row = e >> 2, c4 = e & 3;
                float4 w = *(const float4*)(Wm + row * NM + k0 + c4 * 4);
                rb[i] = make_uint4(f2tf(w.x), f2tf(w.y), f2tf(w.z), f2tf(w.w));
            }
        }
        const float* A  = As + cur * BM * RS;
        const float* Bb = Bs + cur * NA * RS + (wid * 64) * RS;
#pragma unroll
        for (int kk = 0; kk < KC; kk += 8) {
            unsigned af[4][4];
#pragma unroll
            for (int mf = 0; mf < 4; mf++) {
                af[mf][0] = __float_as_uint(A[(mf * 16 + g) * RS + kk + tg]);
                af[mf][1] = __float_as_uint(A[(mf * 16 + 8 + g) * RS + kk + tg]);
                af[mf][2] = __float_as_uint(A[(mf * 16 + g) * RS + kk + tg + 4]);
                af[mf][3] = __float_as_uint(A[(mf * 16 + 8 + g) * RS + kk + tg + 4]);
            }
#pragma unroll
            for (int j = 0; j < 8; j++) {
                unsigned b0 = __float_as_uint(Bb[(j * 8 + g) * RS + kk + tg]);
                unsigned b1 = __float_as_uint(Bb[(j * 8 + g) * RS + kk + tg + 4]);
#pragma unroll
                for (int mf = 0; mf < 4; mf++)
                    mma_tf32(acc[mf][j][0], acc[mf][j][1], acc[mf][j][2], acc[mf][j][3],
                             af[mf][0], af[mf][1], af[mf][2], af[mf][3], b0, b1);
            }
        }
        __syncthreads();
        if (c < NCHUNK - 1) {
            int nxt = cur ^ 1;
            *(uint4*)(As + nxt * BM * RS + arow * RS + ac4 * 4) = ra;
#pragma unroll
            for (int i = 0; i < 8; i++) {
                int e = tid + i * 256;
                int row = e >> 2, c4 = e & 3;
                *(uint4*)(Bs + nxt * NA * RS + row * RS + c4 * 4) = rb[i];
            }
        }
        __syncthreads();
    }

    // epilogue: score[row] = sum_a Wv[a]*tanh(wq[a] + wm[row][a])
    float p[4][2];
#pragma unroll
    for (int mf = 0; mf < 4; mf++) { p[mf][0] = 0.f; p[mf][1] = 0.f; }
#pragma unroll
    for (int mf = 0; mf < 4; mf++)
#pragma unroll
        for (int j = 0; j < 8; j++) {
            int a0 = wid * 64 + j * 8 + 2 * tg;
            float w0 = wvs[a0], w1 = wvs[a0 + 1];
            float q0 = wqs[a0], q1 = wqs[a0 + 1];
            p[mf][0] += w0 * tanhf(q0 + acc[mf][j][0]) + w1 * tanhf(q1 + acc[mf][j][1]);
            p[mf][1] += w0 * tanhf(q0 + acc[mf][j][2]) + w1 * tanhf(q1 + acc[mf][j][3]);
        }
#pragma unroll
    for (int mf = 0; mf < 4; mf++)
#pragma unroll
        for (int h = 0; h < 2; h++) {
            p[mf][h] += __shfl_xor_sync(0xffffffffu, p[mf][h], 1);
            p[mf][h] += __shfl_xor_sync(0xffffffffu, p[mf][h], 2);
        }
    if (tg == 0) {
#pragma unroll
        for (int mf = 0; mf < 4; mf++)
#pragma unroll
            for (int h = 0; h < 2; h++)
                sp[wid * 64 + mf * 16 + h * 8 + g] = p[mf][h];
    }
    __syncthreads();
    if (tid < BM) {
        float s = 0.f;
#pragma unroll
        for (int w = 0; w < 8; w++) s += sp[w * 64 + tid];
        scores[b * NT + t0 + tid] = s;
    }
}

// ---------------------------------------------------------------------------
// Kernel 3: in-place softmax over T per batch row
// ---------------------------------------------------------------------------
__global__ void softmax_kernel(float* __restrict__ sc) {
    int b = blockIdx.x;
    float* row = sc + b * NT;
    int tid = threadIdx.x;  // 256
    __shared__ float red[8];
    float v[8];
    float m = -3.0e38f;
#pragma unroll
    for (int i = 0; i < 8; i++) { v[i] = row[tid + 256 * i]; m = fmaxf(m, v[i]); }
#pragma unroll
    for (int o = 16; o; o >>= 1) m = fmaxf(m, __shfl_xor_sync(0xffffffffu, m, o));
    if ((tid & 31) == 0) red[tid >> 5] = m;
    __syncthreads();
    m = red[0];
#pragma unroll
    for (int w = 1; w < 8; w++) m = fmaxf(m, red[w]);
    __syncthreads();
    float s = 0.f;
#pragma unroll
    for (int i = 0; i < 8; i++) { v[i] = expf(v[i] - m); s += v[i]; }
#pragma unroll
    for (int o = 16; o; o >>= 1) s += __shfl_xor_sync(0xffffffffu, s, o);
    if ((tid & 31) == 0) red[tid >> 5] = s;
    __syncthreads();
    s = 0.f;
#pragma unroll
    for (int w = 0; w < 8; w++) s += red[w];
    float inv = 1.f / s;
#pragma unroll
    for (int i = 0; i < 8; i++) row[tid + 256 * i] = v[i] * inv;
}

// ---------------------------------------------------------------------------
// Kernel 4: context[b][m] = sum_t alpha[b][t] * memory[b][t][m]
// ---------------------------------------------------------------------------
__global__ void context_kernel(const float* __restrict__ mem,
                               const float* __restrict__ alpha,
                               float* __restrict__ ctx) {
    __shared__ float al[NT];
    int b = blockIdx.y;
    int m = blockIdx.x * 128 + threadIdx.x;
    for (int i = threadIdx.x; i < NT; i += 128) al[i] = alpha[b * NT + i];
    __syncthreads();
    const float* mp = mem + (size_t)b * NT * NM + m;
    float a0 = 0.f, a1 = 0.f, a2 = 0.f, a3 = 0.f;
#pragma unroll 2
    for (int t = 0; t < NT; t += 4) {
        a0 += al[t]     * mp[(size_t)(t)     * NM];
        a1 += al[t + 1] * mp[(size_t)(t + 1) * NM];
        a2 += al[t + 2] * mp[(size_t)(t + 2) * NM];
        a3 += al[t + 3] * mp[(size_t)(t + 3) * NM];
    }
    ctx[b * NM + m] = (a0 + a1) + (a2 + a3);
}

// ---------------------------------------------------------------------------
extern "C" void kernel_launch(void* const* d_in, const int* in_sizes, int n_in,
                              void* d_out, int out_size) {
    const float* query  = (const float*)d_in[0];
    const float* memory = (const float*)d_in[1];
    const float* Wq     = (const float*)d_in[2];
    const float* Wm     = (const float*)d_in[3];
    const float* Wv     = (const float*)d_in[4];
    float* alpha = (float*)d_out;            // [64, 2048]
    float* ctx   = alpha + NB * NT;          // [64, 1024]

    wq_kernel<<<NB, NA>>>(query, Wq);

    int smembytes = (2 * BM * RS + 2 * NA * RS + NA + NA + 8 * 64) * (int)sizeof(float);
    cudaFuncSetAttribute(score_kernel, cudaFuncAttributeMaxDynamicSharedMemorySize, smembytes);
    score_kernel<<<dim3(NT / BM, NB), 256, smembytes>>>(memory, Wm, Wv, alpha);

    softmax_kernel<<<NB, 256>>>(alpha);
    context_kernel<<<dim3(NM / 128, NB), 128>>>(memory, alpha, ctx);
}

// round 3
// speedup vs baseline: 1.4837x; 1.4837x over previous
#include <cuda_runtime.h>
#include <cstdint>

#define NB 64
#define NT 2048
#define NM 1024
#define NA 512
#define NQ 1024

#define BM 64            // t-rows per CTA
#define KC 16            // k per stage
#define NCHUNK (NM / KC) // 64
#define RS 20            // smem row stride (floats): conflict-free, 16B-aligned
#define NSTAGE 3

#define A_ST (BM * RS)          // 1280 floats per A stage
#define B_ST (NA * RS)          // 10240 floats per B stage
#define OFF_A 0
#define OFF_B (NSTAGE * A_ST)                 // 3840
#define OFF_WQ (OFF_B + NSTAGE * B_ST)        // 34560
#define OFF_WV (OFF_WQ + NA)
#define OFF_SP (OFF_WV + NA)                  // 16 warps x 64 rows
#define SMEM_FLOATS (OFF_SP + 16 * 64)
#define SMEM_SZ (SMEM_FLOATS * 4)             // 146432 bytes

__device__ float g_wq[NB * NA];
__device__ float g_ctxp[8 * NB * NM];   // context partials [ts][b][m]

__device__ __forceinline__ uint32_t smem_u32(const void* p) {
    uint32_t a;
    asm("{ .reg .u64 t; cvta.to.shared.u64 t, %1; cvt.u32.u64 %0, t; }" : "=r"(a) : "l"(p));
    return a;
}

__device__ __forceinline__ void cpasync16(uint32_t dst, const void* src) {
    asm volatile("cp.async.cg.shared.global [%0], [%1], 16;" :: "r"(dst), "l"(src) : "memory");
}

__device__ __forceinline__ void mma_tf32(float& d0, float& d1, float& d2, float& d3,
                                         unsigned a0, unsigned a1, unsigned a2, unsigned a3,
                                         unsigned b0, unsigned b1) {
    asm("mma.sync.aligned.m16n8k8.row.col.f32.tf32.tf32.f32 "
        "{%0,%1,%2,%3},{%4,%5,%6,%7},{%8,%9},{%0,%1,%2,%3};"
        : "+f"(d0), "+f"(d1), "+f"(d2), "+f"(d3)
        : "r"(a0), "r"(a1), "r"(a2), "r"(a3), "r"(b0), "r"(b1));
}

// ---------------------------------------------------------------------------
// Kernel 1: wq[b][a] = query[b] . W_query[a]   (fp32 exact, tiny)
// ---------------------------------------------------------------------------
__global__ void wq_kernel(const float* __restrict__ query, const float* __restrict__ Wq) {
    int b = blockIdx.x, a = threadIdx.x;
    const float4* q4 = (const float4*)(query + b * NQ);
    const float4* w4 = (const float4*)(Wq + a * NQ);
    float s = 0.f;
#pragma unroll 8
    for (int k = 0; k < NQ / 4; k++) {
        float4 q = q4[k], w = w4[k];
        s += q.x * w.x + q.y * w.y + q.z * w.z + q.w * w.w;
    }
    g_wq[b * NA + a] = s;
}

// ---------------------------------------------------------------------------
// Kernel 2: fused tf32 mma.sync GEMM (64 x 512 x 1024) + Wv.tanh(wq+wm)
// 512 threads / 16 warps; warp w handles cols [w*32, w*32+32); 64 accums/thr.
// 3-stage cp.async pipeline, KC=16.
// ---------------------------------------------------------------------------
__device__ __forceinline__ void issue_chunk(const float* Ag, const float* Wm, int c,
                                            uint32_t abuf, uint32_t bbuf, int tid) {
    int koff = c * KC;
    if (tid < 256) {   // A: 64 rows x 16 floats = 256 float4
        int row = tid >> 2, c4 = tid & 3;
        cpasync16(abuf + (row * RS + c4 * 4) * 4, Ag + (size_t)row * NM + koff + c4 * 4);
    }
#pragma unroll
    for (int i = 0; i < 4; i++) {  // B: 512 rows x 16 floats = 2048 float4
        int e = tid + i * 512;
        int row = e >> 2, c4 = e & 3;
        cpasync16(bbuf + (row * RS + c4 * 4) * 4, Wm + (size_t)row * NM + koff + c4 * 4);
    }
    asm volatile("cp.async.commit_group;" ::: "memory");
}

__global__ __launch_bounds__(512, 1) void score_kernel(
    const float* __restrict__ mem, const float* __restrict__ Wm,
    const float* __restrict__ Wv, float* __restrict__ scores)
{
    extern __shared__ __align__(16) float smem[];
    uint32_t sbase = smem_u32(smem);
    float* wqs = smem + OFF_WQ;
    float* wvs = smem + OFF_WV;
    float* spr = smem + OFF_SP;

    int tid = threadIdx.x, wid = tid >> 5, lane = tid & 31;
    int g = lane >> 2, tg = lane & 3;
    int b = blockIdx.y, t0 = blockIdx.x * BM;

    for (int i = tid; i < NA; i += 512) {
        wqs[i] = g_wq[b * NA + i];
        wvs[i] = Wv[i];
    }

    const float* Ag = mem + ((size_t)b * NT + t0) * NM;

    float acc[4][4][4];
#pragma unroll
    for (int mf = 0; mf < 4; mf++)
#pragma unroll
        for (int j = 0; j < 4; j++)
#pragma unroll
            for (int q = 0; q < 4; q++) acc[mf][j][q] = 0.f;

    // prologue: stages 0 and 1
    issue_chunk(Ag, Wm, 0, sbase + (OFF_A + 0 * A_ST) * 4, sbase + (OFF_B + 0 * B_ST) * 4, tid);
    issue_chunk(Ag, Wm, 1, sbase + (OFF_A + 1 * A_ST) * 4, sbase + (OFF_B + 1 * B_ST) * 4, tid);

    for (int c = 0; c < NCHUNK; c++) {
        if (c < NCHUNK - 1) asm volatile("cp.async.wait_group 1;" ::: "memory");
        else                asm volatile("cp.async.wait_group 0;" ::: "memory");
        __syncthreads();   // stage c visible to all; all done computing stage c-1
        if (c < NCHUNK - 2) {
            int nb = (c + 2) % NSTAGE;
            issue_chunk(Ag, Wm, c + 2,
                        sbase + (OFF_A + nb * A_ST) * 4, sbase + (OFF_B + nb * B_ST) * 4, tid);
        }
        int cb = c % NSTAGE;
        const float* A  = smem + OFF_A + cb * A_ST;
        const float* Bw = smem + OFF_B + cb * B_ST + (wid * 32) * RS;
#pragma unroll
        for (int kk = 0; kk < KC; kk += 8) {
            unsigned af[4][4];
#pragma unroll
            for (int mf = 0; mf < 4; mf++) {
                af[mf][0] = __float_as_uint(A[(mf * 16 + g) * RS + kk + tg]);
                af[mf][1] = __float_as_uint(A[(mf * 16 + 8 + g) * RS + kk + tg]);
                af[mf][2] = __float_as_uint(A[(mf * 16 + g) * RS + kk + tg + 4]);
                af[mf][3] = __float_as_uint(A[(mf * 16 + 8 + g) * RS + kk + tg + 4]);
            }
#pragma unroll
            for (int j = 0; j < 4; j++) {
                unsigned b0 = __float_as_uint(Bw[(j * 8 + g) * RS + kk + tg]);
                unsigned b1 = __float_as_uint(Bw[(j * 8 + g) * RS + kk + tg + 4]);
#pragma unroll
                for (int mf = 0; mf < 4; mf++)
                    mma_tf32(acc[mf][j][0], acc[mf][j][1], acc[mf][j][2], acc[mf][j][3],
                             af[mf][0], af[mf][1], af[mf][2], af[mf][3], b0, b1);
            }
        }
    }

    // epilogue: partial score rows for this warp's 32 cols
    float p0[4], p1[4];
#pragma unroll
    for (int mf = 0; mf < 4; mf++) { p0[mf] = 0.f; p1[mf] = 0.f; }
#pragma unroll
    for (int mf = 0; mf < 4; mf++)
#pragma unroll
        for (int j = 0; j < 4; j++) {
            int a0 = wid * 32 + j * 8 + 2 * tg;
            float w0 = wvs[a0], w1 = wvs[a0 + 1];
            float q0 = wqs[a0], q1 = wqs[a0 + 1];
            p0[mf] += w0 * tanhf(q0 + acc[mf][j][0]) + w1 * tanhf(q1 + acc[mf][j][1]);
            p1[mf] += w0 * tanhf(q0 + acc[mf][j][2]) + w1 * tanhf(q1 + acc[mf][j][3]);
        }
#pragma unroll
    for (int mf = 0; mf < 4; mf++) {
        p0[mf] += __shfl_xor_sync(0xffffffffu, p0[mf], 1);
        p0[mf] += __shfl_xor_sync(0xffffffffu, p0[mf], 2);
        p1[mf] += __shfl_xor_sync(0xffffffffu, p1[mf], 1);
        p1[mf] += __shfl_xor_sync(0xffffffffu, p1[mf], 2);
    }
    if (tg == 0) {
#pragma unroll
        for (int mf = 0; mf < 4; mf++) {
            spr[wid * 64 + mf * 16 + g]     = p0[mf];
            spr[wid * 64 + mf * 16 + 8 + g] = p1[mf];
        }
    }
    __syncthreads();
    if (tid < BM) {
        float s = 0.f;
#pragma unroll
        for (int w = 0; w < 16; w++) s += spr[w * 64 + tid];
        scores[b * NT + t0 + tid] = s;
    }
}

// ---------------------------------------------------------------------------
// Kernel 3: in-place softmax over T per batch row
// ---------------------------------------------------------------------------
__global__ void softmax_kernel(float* __restrict__ sc) {
    int b = blockIdx.x;
    float* row = sc + b * NT;
    int tid = threadIdx.x;  // 256
    __shared__ float red[8];
    float v[8];
    float m = -3.0e38f;
#pragma unroll
    for (int i = 0; i < 8; i++) { v[i] = row[tid + 256 * i]; m = fmaxf(m, v[i]); }
#pragma unroll
    for (int o = 16; o; o >>= 1) m = fmaxf(m, __shfl_xor_sync(0xffffffffu, m, o));
    if ((tid & 31) == 0) red[tid >> 5] = m;
    __syncthreads();
    m = red[0];
#pragma unroll
    for (int w = 1; w < 8; w++) m = fmaxf(m, red[w]);
    __syncthreads();
    float s = 0.f;
#pragma unroll
    for (int i = 0; i < 8; i++) { v[i] = expf(v[i] - m); s += v[i]; }
#pragma unroll
    for (int o = 16; o; o >>= 1) s += __shfl_xor_sync(0xffffffffu, s, o);
    if ((tid & 31) == 0) red[tid >> 5] = s;
    __syncthreads();
    s = 0.f;
#pragma unroll
    for (int w = 0; w < 8; w++) s += red[w];
    float inv = 1.f / s;
#pragma unroll
    for (int i = 0; i < 8; i++) row[tid + 256 * i] = v[i] * inv;
}

// ---------------------------------------------------------------------------
// Kernel 4: context partials over 8 T-slices (deterministic, no atomics)
// ---------------------------------------------------------------------------
__global__ __launch_bounds__(128) void context_part_kernel(
    const float* __restrict__ mem, const float* __restrict__ alpha)
{
    __shared__ float al[256];
    int b = blockIdx.z, ts = blockIdx.y;
    int m0 = blockIdx.x * 512 + threadIdx.x * 4;
    al[threadIdx.x]       = alpha[b * NT + ts * 256 + threadIdx.x];
    al[threadIdx.x + 128] = alpha[b * NT + ts * 256 + 128 + threadIdx.x];
    __syncthreads();
    const float* mp = mem + ((size_t)b * NT + ts * 256) * NM + m0;
    float4 acc0 = {0.f, 0.f, 0.f, 0.f}, acc1 = {0.f, 0.f, 0.f, 0.f};
#pragma unroll 4
    for (int t = 0; t < 256; t += 2) {
        float a0 = al[t], a1 = al[t + 1];
        float4 v0 = *(const float4*)(mp + (size_t)t * NM);
        float4 v1 = *(const float4*)(mp + (size_t)(t + 1) * NM);
        acc0.x += a0 * v0.x; acc0.y += a0 * v0.y; acc0.z += a0 * v0.z; acc0.w += a0 * v0.w;
        acc1.x += a1 * v1.x; acc1.y += a1 * v1.y; acc1.z += a1 * v1.z; acc1.w += a1 * v1.w;
    }
    float4 out;
    out.x = acc0.x + acc1.x; out.y = acc0.y + acc1.y;
    out.z = acc0.z + acc1.z; out.w = acc0.w + acc1.w;
    *(float4*)(g_ctxp + ((size_t)ts * NB + b) * NM + m0) = out;
}

__global__ void ctx_reduce_kernel(float* __restrict__ ctx) {
    int b = blockIdx.x, m = threadIdx.x;
    float s = 0.f;
#pragma unroll
    for (int ts = 0; ts < 8; ts++)
        s += g_ctxp[((size_t)ts * NB + b) * NM + m];
    ctx[b * NM + m] = s;
}

// ---------------------------------------------------------------------------
extern "C" void kernel_launch(void* const* d_in, const int* in_sizes, int n_in,
                              void* d_out, int out_size) {
    const float* query  = (const float*)d_in[0];
    const float* memory = (const float*)d_in[1];
    const float* Wq     = (const float*)d_in[2];
    const float* Wm     = (const float*)d_in[3];
    const float* Wv     = (const float*)d_in[4];
    float* alpha = (float*)d_out;            // [64, 2048]
    float* ctx   = alpha + NB * NT;          // [64, 1024]

    wq_kernel<<<NB, NA>>>(query, Wq);

    cudaFuncSetAttribute(score_kernel, cudaFuncAttributeMaxDynamicSharedMemorySize, SMEM_SZ);
    score_kernel<<<dim3(NT / BM, NB), 512, SMEM_SZ>>>(memory, Wm, Wv, alpha);

    softmax_kernel<<<NB, 256>>>(alpha);
    context_part_kernel<<<dim3(2, 8, NB), 128>>>(memory, alpha);
    ctx_reduce_kernel<<<NB, NM>>>(ctx);
}

// round 4
// speedup vs baseline: 2.4005x; 1.6179x over previous
#include <cuda_runtime.h>
#include <cuda_fp16.h>
#include <cstdint>

#define NB 64
#define NT 2048
#define NM 1024
#define NA 512
#define NQ 1024

#define BM 64             // t-rows per CTA
#define KC 32             // k per stage (fp16: 2 MMA k-steps)
#define NCHUNK (NM / KC)  // 32
#define RS 20             // smem row stride in uints (half2): conflict-free, 16B-aligned
#define NBST 3            // B stages

#define A_ST (BM * RS)                   // 1280 uints per A stage
#define B_ST (NA * RS)                   // 10240 uints per B stage
#define OFF_A 0
#define OFF_B (2 * A_ST)                 // 2560
#define OFF_WQ (OFF_B + NBST * B_ST)     // 33280 (floats from here)
#define OFF_WV (OFF_WQ + NA)
#define OFF_SP (OFF_WV + NA)
#define SMEM_WORDS (OFF_SP + 16 * 64)
#define SMEM_SZ (SMEM_WORDS * 4)         // ~141 KB

__device__ float g_wq[NB * NA];
__device__ uint32_t g_wm_h[NA * NM / 2];   // Wm as half2 pairs, [a][k/2]
__device__ float g_ctxp[8 * NB * NM];      // context partials [ts][b][m]

__device__ __forceinline__ uint32_t smem_u32(const void* p) {
    uint32_t a;
    asm("{ .reg .u64 t; cvta.to.shared.u64 t, %1; cvt.u32.u64 %0, t; }" : "=r"(a) : "l"(p));
    return a;
}

__device__ __forceinline__ void cpasync16(uint32_t dst, const void* src) {
    asm volatile("cp.async.cg.shared.global [%0], [%1], 16;" :: "r"(dst), "l"(src) : "memory");
}

__device__ __forceinline__ uint32_t pack_h2(float x, float y) {
    __half2 h = __floats2half2_rn(x, y);
    return *(uint32_t*)&h;
}

__device__ __forceinline__ void mma_f16(float& d0, float& d1, float& d2, float& d3,
                                        unsigned a0, unsigned a1, unsigned a2, unsigned a3,
                                        unsigned b0, unsigned b1) {
    asm("mma.sync.aligned.m16n8k16.row.col.f32.f16.f16.f32 "
        "{%0,%1,%2,%3},{%4,%5,%6,%7},{%8,%9},{%0,%1,%2,%3};"
        : "+f"(d0), "+f"(d1), "+f"(d2), "+f"(d3)
        : "r"(a0), "r"(a1), "r"(a2), "r"(a3), "r"(b0), "r"(b1));
}

// ---------------------------------------------------------------------------
// Kernel 0: convert Wm (fp32) -> g_wm_h (half2 pairs)
// ---------------------------------------------------------------------------
__global__ void cvt_wm_kernel(const float* __restrict__ Wm) {
    int i = blockIdx.x * 256 + threadIdx.x;   // 65536 threads, 8 floats each
    const float4* s = (const float4*)Wm;
    float4 v0 = s[2 * i], v1 = s[2 * i + 1];
    g_wm_h[4 * i + 0] = pack_h2(v0.x, v0.y);
    g_wm_h[4 * i + 1] = pack_h2(v0.z, v0.w);
    g_wm_h[4 * i + 2] = pack_h2(v1.x, v1.y);
    g_wm_h[4 * i + 3] = pack_h2(v1.z, v1.w);
}

// ---------------------------------------------------------------------------
// Kernel 1: wq[b][a] = query[b] . W_query[a]   (fp32 exact, tiny)
// ---------------------------------------------------------------------------
__global__ void wq_kernel(const float* __restrict__ query, const float* __restrict__ Wq) {
    int b = blockIdx.x, a = threadIdx.x;
    const float4* q4 = (const float4*)(query + b * NQ);
    const float4* w4 = (const float4*)(Wq + a * NQ);
    float s = 0.f;
#pragma unroll 8
    for (int k = 0; k < NQ / 4; k++) {
        float4 q = q4[k], w = w4[k];
        s += q.x * w.x + q.y * w.y + q.z * w.z + q.w * w.w;
    }
    g_wq[b * NA + a] = s;
}

// ---------------------------------------------------------------------------
// Kernel 2: fused fp16 mma.sync GEMM (64 x 512 x 1024) + Wv.tanh(wq+wm)
// 512 threads / 16 warps; warp w: cols [w*32, w*32+32); 64 fp32 accs/thread.
// B: 3-stage cp.async from pre-converted g_wm_h; A: LDG->cvt->STS, 2 buffers.
// ---------------------------------------------------------------------------
__device__ __forceinline__ void issue_B(int c, uint32_t bbuf, int tid) {
    int k2 = c * (KC / 2);                    // uint offset within row
#pragma unroll
    for (int i = 0; i < 4; i++) {             // 512 rows x 4 x 16B
        int e = tid + i * 512;
        int row = e >> 2, c16 = e & 3;
        cpasync16(bbuf + (row * RS + c16 * 4) * 4,
                  g_wm_h + (size_t)row * (NM / 2) + k2 + c16 * 4);
    }
    asm volatile("cp.async.commit_group;" ::: "memory");
}

__global__ __launch_bounds__(512, 1) void score_kernel(
    const float* __restrict__ mem, const float* __restrict__ Wv,
    float* __restrict__ scores)
{
    extern __shared__ __align__(16) uint32_t smem[];
    uint32_t sbase = smem_u32(smem);
    float* wqs = (float*)(smem + OFF_WQ);
    float* wvs = (float*)(smem + OFF_WV);
    float* spr = (float*)(smem + OFF_SP);

    int tid = threadIdx.x, wid = tid >> 5, lane = tid & 31;
    int g = lane >> 2, tg = lane & 3;
    int b = blockIdx.y, t0 = blockIdx.x * BM;

    for (int i = tid; i < NA; i += 512) {
        wqs[i] = g_wq[b * NA + i];
        wvs[i] = Wv[i];
    }

    const float* Ag = mem + ((size_t)b * NT + t0) * NM;
    const int arow = tid >> 3, ac4 = tid & 7;   // A: 64 rows x 8 float4

    float acc[4][4][4];
#pragma unroll
    for (int mf = 0; mf < 4; mf++)
#pragma unroll
        for (int j = 0; j < 4; j++)
#pragma unroll
            for (int q = 0; q < 4; q++) acc[mf][j][q] = 0.f;

    // prologue
    float4 ar = *(const float4*)(Ag + (size_t)arow * NM + ac4 * 4);   // A chunk 0
    issue_B(0, sbase + OFF_B * 4, tid);
    issue_B(1, sbase + (OFF_B + B_ST) * 4, tid);

    for (int c = 0; c < NCHUNK; c++) {
        if (c < NCHUNK - 1) asm volatile("cp.async.wait_group 1;" ::: "memory");
        else                asm volatile("cp.async.wait_group 0;" ::: "memory");
        // store A(c) from regs (fp16)
        {
            uint32_t* Ab = smem + OFF_A + (c & 1) * A_ST;
            uint2 u;
            u.x = pack_h2(ar.x, ar.y);
            u.y = pack_h2(ar.z, ar.w);
            *(uint2*)(Ab + arow * RS + ac4 * 2) = u;
        }
        __syncthreads();   // B(c) + A(c) visible; all warps done with c-1 buffers
        if (c < NCHUNK - 1)
            ar = *(const float4*)(Ag + (size_t)arow * NM + (c + 1) * KC + ac4 * 4);
        if (c < NCHUNK - 2)
            issue_B(c + 2, sbase + (OFF_B + ((c + 2) % NBST) * B_ST) * 4, tid);

        const uint32_t* A  = smem + OFF_A + (c & 1) * A_ST;
        const uint32_t* Bw = smem + OFF_B + (c % NBST) * B_ST + (wid * 32) * RS;
#pragma unroll
        for (int ks = 0; ks < 2; ks++) {
            int ko = ks * 8;   // uint offset for this k16 step
            unsigned af[4][4];
#pragma unroll
            for (int mf = 0; mf < 4; mf++) {
                af[mf][0] = A[(mf * 16 + g) * RS + ko + tg];
                af[mf][1] = A[(mf * 16 + 8 + g) * RS + ko + tg];
                af[mf][2] = A[(mf * 16 + g) * RS + ko + tg + 4];
                af[mf][3] = A[(mf * 16 + 8 + g) * RS + ko + tg + 4];
            }
#pragma unroll
            for (int j = 0; j < 4; j++) {
                unsigned b0 = Bw[(j * 8 + g) * RS + ko + tg];
                unsigned b1 = Bw[(j * 8 + g) * RS + ko + tg + 4];
#pragma unroll
                for (int mf = 0; mf < 4; mf++)
                    mma_f16(acc[mf][j][0], acc[mf][j][1], acc[mf][j][2], acc[mf][j][3],
                            af[mf][0], af[mf][1], af[mf][2], af[mf][3], b0, b1);
            }
        }
    }

    // epilogue: partial score rows for this warp's 32 cols
    float p0[4], p1[4];
#pragma unroll
    for (int mf = 0; mf < 4; mf++) { p0[mf] = 0.f; p1[mf] = 0.f; }
#pragma unroll
    for (int mf = 0; mf < 4; mf++)
#pragma unroll
        for (int j = 0; j < 4; j++) {
            int a0 = wid * 32 + j * 8 + 2 * tg;
            float w0 = wvs[a0], w1 = wvs[a0 + 1];
            float q0 = wqs[a0], q1 = wqs[a0 + 1];
            p0[mf] += w0 * tanhf(q0 + acc[mf][j][0]) + w1 * tanhf(q1 + acc[mf][j][1]);
            p1[mf] += w0 * tanhf(q0 + acc[mf][j][2]) + w1 * tanhf(q1 + acc[mf][j][3]);
        }
#pragma unroll
    for (int mf = 0; mf < 4; mf++) {
        p0[mf] += __shfl_xor_sync(0xffffffffu, p0[mf], 1);
        p0[mf] += __shfl_xor_sync(0xffffffffu, p0[mf], 2);
        p1[mf] += __shfl_xor_sync(0xffffffffu, p1[mf], 1);
        p1[mf] += __shfl_xor_sync(0xffffffffu, p1[mf], 2);
    }
    if (tg == 0) {
#pragma unroll
        for (int mf = 0; mf < 4; mf++) {
            spr[wid * 64 + mf * 16 + g]     = p0[mf];
            spr[wid * 64 + mf * 16 + 8 + g] = p1[mf];
        }
    }
    __syncthreads();
    if (tid < BM) {
        float s = 0.f;
#pragma unroll
        for (int w = 0; w < 16; w++) s += spr[w * 64 + tid];
        scores[b * NT + t0 + tid] = s;
    }
}

// ---------------------------------------------------------------------------
// Kernel 3: in-place softmax over T per batch row
// ---------------------------------------------------------------------------
__global__ void softmax_kernel(float* __restrict__ sc) {
    int b = blockIdx.x;
    float* row = sc + b * NT;
    int tid = threadIdx.x;  // 256
    __shared__ float red[8];
    float v[8];
    float m = -3.0e38f;
#pragma unroll
    for (int i = 0; i < 8; i++) { v[i] = row[tid + 256 * i]; m = fmaxf(m, v[i]); }
#pragma unroll
    for (int o = 16; o; o >>= 1) m = fmaxf(m, __shfl_xor_sync(0xffffffffu, m, o));
    if ((tid & 31) == 0) red[tid >> 5] = m;
    __syncthreads();
    m = red[0];
#pragma unroll
    for (int w = 1; w < 8; w++) m = fmaxf(m, red[w]);
    __syncthreads();
    float s = 0.f;
#pragma unroll
    for (int i = 0; i < 8; i++) { v[i] = expf(v[i] - m); s += v[i]; }
#pragma unroll
    for (int o = 16; o; o >>= 1) s += __shfl_xor_sync(0xffffffffu, s, o);
    if ((tid & 31) == 0) red[tid >> 5] = s;
    __syncthreads();
    s = 0.f;
#pragma unroll
    for (int w = 0; w < 8; w++) s += red[w];
    float inv = 1.f / s;
#pragma unroll
    for (int i = 0; i < 8; i++) row[tid + 256 * i] = v[i] * inv;
}

// ---------------------------------------------------------------------------
// Kernel 4: context partials over 8 T-slices (deterministic)
// ---------------------------------------------------------------------------
__global__ __launch_bounds__(128) void context_part_kernel(
    const float* __restrict__ mem, const float* __restrict__ alpha)
{
    __shared__ float al[256];
    int b = blockIdx.z, ts = blockIdx.y;
    int m0 = blockIdx.x * 512 + threadIdx.x * 4;
    al[threadIdx.x]       = alpha[b * NT + ts * 256 + threadIdx.x];
    al[threadIdx.x + 128] = alpha[b * NT + ts * 256 + 128 + threadIdx.x];
    __syncthreads();
    const float* mp = mem + ((size_t)b * NT + ts * 256) * NM + m0;
    float4 acc0 = {0.f, 0.f, 0.f, 0.f}, acc1 = {0.f, 0.f, 0.f, 0.f};
#pragma unroll 4
    for (int t = 0; t < 256; t += 2) {
        float a0 = al[t], a1 = al[t + 1];
        float4 v0 = *(const float4*)(mp + (size_t)t * NM);
        float4 v1 = *(const float4*)(mp + (size_t)(t + 1) * NM);
        acc0.x += a0 * v0.x; acc0.y += a0 * v0.y; acc0.z += a0 * v0.z; acc0.w += a0 * v0.w;
        acc1.x += a1 * v1.x; acc1.y += a1 * v1.y; acc1.z += a1 * v1.z; acc1.w += a1 * v1.w;
    }
    float4 out;
    out.x = acc0.x + acc1.x; out.y = acc0.y + acc1.y;
    out.z = acc0.z + acc1.z; out.w = acc0.w + acc1.w;
    *(float4*)(g_ctxp + ((size_t)ts * NB + b) * NM + m0) = out;
}

__global__ void ctx_reduce_kernel(float* __restrict__ ctx) {
    int b = blockIdx.x, m = threadIdx.x;
    float s = 0.f;
#pragma unroll
    for (int ts = 0; ts < 8; ts++)
        s += g_ctxp[((size_t)ts * NB + b) * NM + m];
    ctx[b * NM + m] = s;
}

// ---------------------------------------------------------------------------
extern "C" void kernel_launch(void* const* d_in, const int* in_sizes, int n_in,
                              void* d_out, int out_size) {
    const float* query  = (const float*)d_in[0];
    const float* memory = (const float*)d_in[1];
    const float* Wq     = (const float*)d_in[2];
    const float* Wm     = (const float*)d_in[3];
    const float* Wv     = (const float*)d_in[4];
    float* alpha = (float*)d_out;            // [64, 2048]
    float* ctx   = alpha + NB * NT;          // [64, 1024]

    cvt_wm_kernel<<<256, 256>>>(Wm);
    wq_kernel<<<NB, NA>>>(query, Wq);

    cudaFuncSetAttribute(score_kernel, cudaFuncAttributeMaxDynamicSharedMemorySize, SMEM_SZ);
    score_kernel<<<dim3(NT / BM, NB), 512, SMEM_SZ>>>(memory, Wv, alpha);

    softmax_kernel<<<NB, 256>>>(alpha);
    context_part_kernel<<<dim3(2, 8, NB), 128>>>(memory, alpha);
    ctx_reduce_kernel<<<NB, NM>>>(ctx);
}

// round 6
// speedup vs baseline: 2.4829x; 1.0343x over previous
#include <cuda_runtime.h>
#include <cuda_fp16.h>
#include <cstdint>

#define NB 64
#define NT 2048
#define NM 1024
#define NA 512
#define NQ 1024

#define BM 64             // t-rows per CTA
#define KC 32             // k per stage (fp16: 2 MMA k-steps)
#define NCHUNK (NM / KC)  // 32
#define RS 20             // smem row stride in uints (half2): conflict-free, 16B-aligned
#define NBST 4            // B stages (ring)

#define A_ST (BM * RS)                   // 1280 uints per A stage
#define B_ST (NA * RS)                   // 10240 uints per B stage
#define OFF_A 0
#define OFF_B (2 * A_ST)                 // 2560
#define OFF_WQ (OFF_B + NBST * B_ST)     // floats from here
#define OFF_WV (OFF_WQ + NA)
#define OFF_SP (OFF_WV + NA)
#define SMEM_WORDS (OFF_SP + 16 * 64)
#define SMEM_SZ (SMEM_WORDS * 4)         // ~178 KB

__device__ float g_wq[NB * NA];
__device__ uint32_t g_wm_h[NA * NM / 2];   // Wm as half2 pairs, [a][k/2]
__device__ float g_ctxp[8 * NB * NM];      // context partials [ts][b][m]

__device__ __forceinline__ uint32_t smem_u32(const void* p) {
    uint32_t a;
    asm("{ .reg .u64 t; cvta.to.shared.u64 t, %1; cvt.u32.u64 %0, t; }" : "=r"(a) : "l"(p));
    return a;
}

__device__ __forceinline__ void cpasync16(uint32_t dst, const void* src) {
    asm volatile("cp.async.cg.shared.global [%0], [%1], 16;" :: "r"(dst), "l"(src) : "memory");
}

__device__ __forceinline__ uint32_t pack_h2(float x, float y) {
    __half2 h = __floats2half2_rn(x, y);
    return *(uint32_t*)&h;
}

__device__ __forceinline__ void mma_f16(float& d0, float& d1, float& d2, float& d3,
                                        unsigned a0, unsigned a1, unsigned a2, unsigned a3,
                                        unsigned b0, unsigned b1) {
    asm("mma.sync.aligned.m16n8k16.row.col.f32.f16.f16.f32 "
        "{%0,%1,%2,%3},{%4,%5,%6,%7},{%8,%9},{%0,%1,%2,%3};"
        : "+f"(d0), "+f"(d1), "+f"(d2), "+f"(d3)
        : "r"(a0), "r"(a1), "r"(a2), "r"(a3), "r"(b0), "r"(b1));
}

// ---------------------------------------------------------------------------
// Kernel 0: convert Wm (fp32) -> g_wm_h (half2 pairs)
// ---------------------------------------------------------------------------
__global__ void cvt_wm_kernel(const float* __restrict__ Wm) {
    int i = blockIdx.x * 256 + threadIdx.x;
    const float4* s = (const float4*)Wm;
    float4 v0 = s[2 * i], v1 = s[2 * i + 1];
    g_wm_h[4 * i + 0] = pack_h2(v0.x, v0.y);
    g_wm_h[4 * i + 1] = pack_h2(v0.z, v0.w);
    g_wm_h[4 * i + 2] = pack_h2(v1.x, v1.y);
    g_wm_h[4 * i + 3] = pack_h2(v1.z, v1.w);
}

// ---------------------------------------------------------------------------
// Kernel 1: wq[b][a] = query[b] . W_query[a]   (fp32 exact, tiny)
// ---------------------------------------------------------------------------
__global__ void wq_kernel(const float* __restrict__ query, const float* __restrict__ Wq) {
    int b = blockIdx.x, a = threadIdx.x;
    const float4* q4 = (const float4*)(query + b * NQ);
    const float4* w4 = (const float4*)(Wq + a * NQ);
    float s = 0.f;
#pragma unroll 8
    for (int k = 0; k < NQ / 4; k++) {
        float4 q = q4[k], w = w4[k];
        s += q.x * w.x + q.y * w.y + q.z * w.z + q.w * w.w;
    }
    g_wq[b * NA + a] = s;
}

// ---------------------------------------------------------------------------
// Kernel 2: fused fp16 mma.sync GEMM (64 x 512 x 1024) + Wv.tanh(wq+wm)
// 512 threads / 16 warps; warp w: cols [w*32, w*32+32); 64 fp32 accs/thread.
// B: 4-stage cp.async ring, steady-state wait_group 2  (B(c+1),B(c+2) in flight)
// A: 2-chunk register prefetch -> fp16 STS, double buffer.
// Group accounting: at top of iter c, committed = B0..B(c+2); B(c) complete
// requires wait_group <= 2.
// ---------------------------------------------------------------------------
__device__ __forceinline__ void issue_B(int c, uint32_t bbuf, int tid) {
    int k2 = c * (KC / 2);                    // uint offset within row
#pragma unroll
    for (int i = 0; i < 4; i++) {             // 512 rows x 4 x 16B
        int e = tid + i * 512;
        int row = e >> 2, c16 = e & 3;
        cpasync16(bbuf + (row * RS + c16 * 4) * 4,
                  g_wm_h + (size_t)row * (NM / 2) + k2 + c16 * 4);
    }
    asm volatile("cp.async.commit_group;" ::: "memory");
}

__global__ __launch_bounds__(512, 1) void score_kernel(
    const float* __restrict__ mem, const float* __restrict__ Wv,
    float* __restrict__ scores)
{
    extern __shared__ __align__(16) uint32_t smem[];
    uint32_t sbase = smem_u32(smem);
    float* wqs = (float*)(smem + OFF_WQ);
    float* wvs = (float*)(smem + OFF_WV);
    float* spr = (float*)(smem + OFF_SP);

    int tid = threadIdx.x, wid = tid >> 5, lane = tid & 31;
    int g = lane >> 2, tg = lane & 3;
    int b = blockIdx.y, t0 = blockIdx.x * BM;

    for (int i = tid; i < NA; i += 512) {
        wqs[i] = g_wq[b * NA + i];
        wvs[i] = Wv[i];
    }

    const float* Ag = mem + ((size_t)b * NT + t0) * NM;
    const int arow = tid >> 3, ac4 = tid & 7;   // A: 64 rows x 8 float4

    float acc[4][4][4];
#pragma unroll
    for (int mf = 0; mf < 4; mf++)
#pragma unroll
        for (int j = 0; j < 4; j++)
#pragma unroll
            for (int q = 0; q < 4; q++) acc[mf][j][q] = 0.f;

    // prologue: A two chunks deep in regs; B three stages deep in smem
    float4 ar0 = *(const float4*)(Ag + (size_t)arow * NM + ac4 * 4);            // A(0)
    float4 ar1 = *(const float4*)(Ag + (size_t)arow * NM + KC + ac4 * 4);       // A(1)
    issue_B(0, sbase + (OFF_B + 0 * B_ST) * 4, tid);
    issue_B(1, sbase + (OFF_B + 1 * B_ST) * 4, tid);
    issue_B(2, sbase + (OFF_B + 2 * B_ST) * 4, tid);

    for (int c = 0; c < NCHUNK; c++) {
        // guarantee B(c) landed: committed = B0..B(c+2)  ->  allow 2 pending
        if (c < NCHUNK - 2)      asm volatile("cp.async.wait_group 2;" ::: "memory");
        else if (c < NCHUNK - 1) asm volatile("cp.async.wait_group 1;" ::: "memory");
        else                     asm volatile("cp.async.wait_group 0;" ::: "memory");
        // store A(c) from regs (fp16)
        {
            uint32_t* Ab = smem + OFF_A + (c & 1) * A_ST;
            uint2 u;
            u.x = pack_h2(ar0.x, ar0.y);
            u.y = pack_h2(ar0.z, ar0.w);
            *(uint2*)(Ab + arow * RS + ac4 * 2) = u;
        }
        __syncthreads();   // B(c)+A(c) visible; all warps done with stage (c-1)%4 and A(c-1)
        ar0 = ar1;
        if (c < NCHUNK - 2)
            ar1 = *(const float4*)(Ag + (size_t)arow * NM + (c + 2) * KC + ac4 * 4);
        if (c < NCHUNK - 3)
            issue_B(c + 3, sbase + (OFF_B + ((c + 3) % NBST) * B_ST) * 4, tid);

        const uint32_t* A  = smem + OFF_A + (c & 1) * A_ST;
        const uint32_t* Bw = smem + OFF_B + (c % NBST) * B_ST + (wid * 32) * RS;
#pragma unroll
        for (int ks = 0; ks < 2; ks++) {
            int ko = ks * 8;   // uint offset for this k16 step
            unsigned af[4][4];
#pragma unroll
            for (int mf = 0; mf < 4; mf++) {
                af[mf][0] = A[(mf * 16 + g) * RS + ko + tg];
                af[mf][1] = A[(mf * 16 + 8 + g) * RS + ko + tg];
                af[mf][2] = A[(mf * 16 + g) * RS + ko + tg + 4];
                af[mf][3] = A[(mf * 16 + 8 + g) * RS + ko + tg + 4];
            }
#pragma unroll
            for (int j = 0; j < 4; j++) {
                unsigned b0 = Bw[(j * 8 + g) * RS + ko + tg];
                unsigned b1 = Bw[(j * 8 + g) * RS + ko + tg + 4];
#pragma unroll
                for (int mf = 0; mf < 4; mf++)
                    mma_f16(acc[mf][j][0], acc[mf][j][1], acc[mf][j][2], acc[mf][j][3],
                            af[mf][0], af[mf][1], af[mf][2], af[mf][3], b0, b1);
            }
        }
    }

    // epilogue: partial score rows for this warp's 32 cols
    float p0[4], p1[4];
#pragma unroll
    for (int mf = 0; mf < 4; mf++) { p0[mf] = 0.f; p1[mf] = 0.f; }
#pragma unroll
    for (int mf = 0; mf < 4; mf++)
#pragma unroll
        for (int j = 0; j < 4; j++) {
            int a0 = wid * 32 + j * 8 + 2 * tg;
            float w0 = wvs[a0], w1 = wvs[a0 + 1];
            float q0 = wqs[a0], q1 = wqs[a0 + 1];
            p0[mf] += w0 * tanhf(q0 + acc[mf][j][0]) + w1 * tanhf(q1 + acc[mf][j][1]);
            p1[mf] += w0 * tanhf(q0 + acc[mf][j][2]) + w1 * tanhf(q1 + acc[mf][j][3]);
        }
#pragma unroll
    for (int mf = 0; mf < 4; mf++) {
        p0[mf] += __shfl_xor_sync(0xffffffffu, p0[mf], 1);
        p0[mf] += __shfl_xor_sync(0xffffffffu, p0[mf], 2);
        p1[mf] += __shfl_xor_sync(0xffffffffu, p1[mf], 1);
        p1[mf] += __shfl_xor_sync(0xffffffffu, p1[mf], 2);
    }
    if (tg == 0) {
#pragma unroll
        for (int mf = 0; mf < 4; mf++) {
            spr[wid * 64 + mf * 16 + g]     = p0[mf];
            spr[wid * 64 + mf * 16 + 8 + g] = p1[mf];
        }
    }
    __syncthreads();
    if (tid < BM) {
        float s = 0.f;
#pragma unroll
        for (int w = 0; w < 16; w++) s += spr[w * 64 + tid];
        scores[b * NT + t0 + tid] = s;
    }
}

// ---------------------------------------------------------------------------
// Kernel 3: in-place softmax over T per batch row
// ---------------------------------------------------------------------------
__global__ void softmax_kernel(float* __restrict__ sc) {
    int b = blockIdx.x;
    float* row = sc + b * NT;
    int tid = threadIdx.x;  // 256
    __shared__ float red[8];
    float v[8];
    float m = -3.0e38f;
#pragma unroll
    for (int i = 0; i < 8; i++) { v[i] = row[tid + 256 * i]; m = fmaxf(m, v[i]); }
#pragma unroll
    for (int o = 16; o; o >>= 1) m = fmaxf(m, __shfl_xor_sync(0xffffffffu, m, o));
    if ((tid & 31) == 0) red[tid >> 5] = m;
    __syncthreads();
    m = red[0];
#pragma unroll
    for (int w = 1; w < 8; w++) m = fmaxf(m, red[w]);
    __syncthreads();
    float s = 0.f;
#pragma unroll
    for (int i = 0; i < 8; i++) { v[i] = expf(v[i] - m); s += v[i]; }
#pragma unroll
    for (int o = 16; o; o >>= 1) s += __shfl_xor_sync(0xffffffffu, s, o);
    if ((tid & 31) == 0) red[tid >> 5] = s;
    __syncthreads();
    s = 0.f;
#pragma unroll
    for (int w = 0; w < 8; w++) s += red[w];
    float inv = 1.f / s;
#pragma unroll
    for (int i = 0; i < 8; i++) row[tid + 256 * i] = v[i] * inv;
}

// ---------------------------------------------------------------------------
// Kernel 4: context partials over 8 T-slices (deterministic)
// ---------------------------------------------------------------------------
__global__ __launch_bounds__(128) void context_part_kernel(
    const float* __restrict__ mem, const float* __restrict__ alpha)
{
    __shared__ float al[256];
    int b = blockIdx.z, ts = blockIdx.y;
    int m0 = blockIdx.x * 512 + threadIdx.x * 4;
    al[threadIdx.x]       = alpha[b * NT + ts * 256 + threadIdx.x];
    al[threadIdx.x + 128] = alpha[b * NT + ts * 256 + 128 + threadIdx.x];
    __syncthreads();
    const float* mp = mem + ((size_t)b * NT + ts * 256) * NM + m0;
    float4 acc0 = {0.f, 0.f, 0.f, 0.f}, acc1 = {0.f, 0.f, 0.f, 0.f};
#pragma unroll 4
    for (int t = 0; t < 256; t += 2) {
        float a0 = al[t], a1 = al[t + 1];
        float4 v0 = *(const float4*)(mp + (size_t)t * NM);
        float4 v1 = *(const float4*)(mp + (size_t)(t + 1) * NM);
        acc0.x += a0 * v0.x; acc0.y += a0 * v0.y; acc0.z += a0 * v0.z; acc0.w += a0 * v0.w;
        acc1.x += a1 * v1.x; acc1.y += a1 * v1.y; acc1.z += a1 * v1.z; acc1.w += a1 * v1.w;
    }
    float4 out;
    out.x = acc0.x + acc1.x; out.y = acc0.y + acc1.y;
    out.z = acc0.z + acc1.z; out.w = acc0.w + acc1.w;
    *(float4*)(g_ctxp + ((size_t)ts * NB + b) * NM + m0) = out;
}

__global__ void ctx_reduce_kernel(float* __restrict__ ctx) {
    int b = blockIdx.x, m = threadIdx.x;
    float s = 0.f;
#pragma unroll
    for (int ts = 0; ts < 8; ts++)
        s += g_ctxp[((size_t)ts * NB + b) * NM + m];
    ctx[b * NM + m] = s;
}

// ---------------------------------------------------------------------------
extern "C" void kernel_launch(void* const* d_in, const int* in_sizes, int n_in,
                              void* d_out, int out_size) {
    const float* query  = (const float*)d_in[0];
    const float* memory = (const float*)d_in[1];
    const float* Wq     = (const float*)d_in[2];
    const float* Wm     = (const float*)d_in[3];
    const float* Wv     = (const float*)d_in[4];
    float* alpha = (float*)d_out;            // [64, 2048]
    float* ctx   = alpha + NB * NT;          // [64, 1024]

    cvt_wm_kernel<<<256, 256>>>(Wm);
    wq_kernel<<<NB, NA>>>(query, Wq);

    cudaFuncSetAttribute(score_kernel, cudaFuncAttributeMaxDynamicSharedMemorySize, SMEM_SZ);
    score_kernel<<<dim3(NT / BM, NB), 512, SMEM_SZ>>>(memory, Wv, alpha);

    softmax_kernel<<<NB, 256>>>(alpha);
    context_part_kernel<<<dim3(2, 8, NB), 128>>>(memory, alpha);
    ctx_reduce_kernel<<<NB, NM>>>(ctx);
}